// round 13
// baseline (speedup 1.0000x reference)
#include <cuda_runtime.h>

// BackEdgeConv2d fused: out = x * !(5 <= boxcount7x7(x >= 128/255, reflect) <= 19)
// x: [16,3,1024,1024] fp32. R12 +: rows padded to 144B; phase 3 = 8 px/thread
// with two aligned LDS.64 and 16-byte SIMD prefix sums (R5-proven math).

#define TILE_W 128
#define TILE_H 64
#define KPAD 3
#define PH (TILE_H + 2*KPAD)        // 70 padded rows
#define WPR 36                      // words per row (144 B); bytes 0..135 valid
#define ROWB 144
#define PPR 18                      // uint2 pairs per row (pair 17 = zero tail)
#define NTHREADS 256

// PTX prmt: guaranteed default-mode semantics incl. selector-bit-3 MSB-replicate.
__device__ __forceinline__ unsigned prmt(unsigned a, unsigned b, unsigned s) {
    unsigned r;
    asm("prmt.b32 %0, %1, %2, %3;" : "=r"(r) : "r"(a), "r"(b), "r"(s));
    return r;
}

__device__ __forceinline__ unsigned pack4(float4 v, float T) {
    // cond = (x >= T) = !signbit(x - T); x==T -> +0 -> 1. Exact.
    unsigned a0 = __float_as_uint(v.x - T);
    unsigned a1 = __float_as_uint(v.y - T);
    unsigned a2 = __float_as_uint(v.z - T);
    unsigned a3 = __float_as_uint(v.w - T);
    unsigned sa = prmt(prmt(a0, a1, 0x0073), prmt(a2, a3, 0x0073), 0x5410);
    return ((~sa) & 0x80808080u) >> 7;          // 1/0 per byte
}

__global__ __launch_bounds__(NTHREADS, 7)
void backedge_kernel(const float* __restrict__ x, float* __restrict__ out,
                     int H, int W) {
    __shared__ __align__(16) unsigned int scond[PH * WPR];      // 10080 B
    __shared__ __align__(16) unsigned int svsum[TILE_H * WPR];  // 9216 B

    const int tid = threadIdx.x;
    const int c0 = blockIdx.x * TILE_W;
    const int r0 = blockIdx.y * TILE_H;
    const long long plane = (long long)blockIdx.z * H * W;
    const float* xp = x + plane;
    float* op = out + plane;
    const float T = 128.0f / 255.0f;

    // ---- Phase 1: padded binary cond map; one word-PAIR (8 px) per task.
    //      cond byte j <-> global col (c0 - 4 + j); pair 17 (bytes 136..143) = 0.
    const bool interior = (c0 >= 4) && (c0 + TILE_W + 4 <= W) &&
                          (r0 >= KPAD) && (r0 + TILE_H + KPAD <= H);
    if (interior) {
        const float* base = xp + (r0 - KPAD) * W + (c0 - 4);
        #pragma unroll 1
        for (int t = tid; t < PH * PPR; t += NTHREADS) {
            int pr = t / PPR;                 // const divisor -> mul.hi
            int pw = t - pr * PPR;
            uint2 cw = make_uint2(0u, 0u);
            if (pw < 17) {
                const float4* p = (const float4*)(base + pr * W + (pw << 3));
                float4 va = p[0], vb = p[1];
                cw.x = pack4(va, T);
                cw.y = pack4(vb, T);
            }
            ((uint2*)scond)[t] = cw;
        }
    } else {
        #pragma unroll 1
        for (int t = tid; t < PH * PPR; t += NTHREADS) {
            int pr = t / PPR;
            int pw = t - pr * PPR;
            uint2 cw = make_uint2(0u, 0u);
            if (pw < 17) {
                int gr = r0 + pr - KPAD;
                int gc = c0 + (pw << 3) - 4;
                float4 va, vb;
                if ((unsigned)gr < (unsigned)H && (unsigned)gc <= (unsigned)(W - 8)) {
                    const float4* p = (const float4*)(xp + gr * W + gc);
                    va = p[0]; vb = p[1];
                } else {
                    int rr = gr < 0 ? -gr : (gr >= H ? 2 * H - 2 - gr : gr);
                    const float* rowp = xp + rr * W;
                    float f[8];
                    #pragma unroll
                    for (int k = 0; k < 8; k++) {
                        int g = gc + k;
                        g = g < 0 ? -g : (g >= W ? 2 * W - 2 - g : g);
                        f[k] = rowp[g];
                    }
                    va = make_float4(f[0], f[1], f[2], f[3]);
                    vb = make_float4(f[4], f[5], f[6], f[7]);
                }
                cw.x = pack4(va, T);
                cw.y = pack4(vb, T);
            }
            ((uint2*)scond)[t] = cw;
        }
    }
    __syncthreads();

    // ---- Phase 2: vertical 7-sum, SIMD bytes, uint2 grid-stride (R12 pattern)
    {
        const uint2* c2 = (const uint2*)scond;
        uint2* v2 = (uint2*)svsum;
        #pragma unroll 1
        for (int wi = tid; wi < TILE_H * PPR; wi += NTHREADS) {
            uint2 s = c2[wi];
            #pragma unroll
            for (int k = 1; k < 7; k++) {
                uint2 a = c2[wi + k * PPR];
                s.x += a.x; s.y += a.y;
            }
            v2[wi] = s;
        }
    }
    __syncthreads();

    // ---- Phase 3: 8 px/thread/row; two aligned LDS.64; 16-byte SIMD prefix
    //      sums (R5 math); byte band mask + prmt sign-replicate select.
    const int tx = tid & 15;        // span: px cols c0+8tx .. c0+8tx+7
    const int ty = tid >> 4;        // 16 row-owners, 4 rows each (stride 16)
    const unsigned char* vsb = (const unsigned char*)svsum;
    const uint2* vrow = (const uint2*)(vsb + ty * ROWB + (tx << 3));
    const float* gp = xp + (long long)(r0 + ty) * W + c0 + (tx << 3);
    float* gop = op + (long long)(r0 + ty) * W + c0 + (tx << 3);

    #pragma unroll
    for (int rr = 0; rr < TILE_H; rr += 16) {
        uint2 lo = vrow[0];             // bytes a0..a7  (8B aligned)
        uint2 hi = vrow[1];             // bytes a8..a15

        // byte prefix sums P0..P15 (max 112 < 128)
        unsigned p0 = lo.x * 0x01010101u;
        unsigned p1 = lo.y * 0x01010101u + prmt(p0, 0, 0x3333);
        unsigned p2 = hi.x * 0x01010101u + prmt(p1, 0, 0x3333);
        unsigned p3 = hi.y * 0x01010101u + prmt(p2, 0, 0x3333);
        // h_i = P[i+7] - P[i]  (window bytes a_{i+1}..a_{i+7})
        unsigned hA = __vsub4(prmt(p1, p2, 0x6543), p0);   // px 0..3
        unsigned hB = __vsub4(prmt(p2, p3, 0x6543), p1);   // px 4..7

        // band 5..19 per byte -> MSB flag (h <= 49, carry-free)
        unsigned mA = (hA + 0x7B7B7B7Bu) & ~(hA + 0x6C6C6C6Cu) & 0x80808080u;
        unsigned mB = (hB + 0x7B7B7B7Bu) & ~(hB + 0x6C6C6C6Cu) & 0x80808080u;

        const float4* gx = (const float4*)gp;
        float4 xa = gx[0], xb = gx[1];

        float4 oa, ob;
        oa.x = __uint_as_float(__float_as_uint(xa.x) & ~prmt(mA, 0, 0x8888));
        oa.y = __uint_as_float(__float_as_uint(xa.y) & ~prmt(mA, 0, 0x9999));
        oa.z = __uint_as_float(__float_as_uint(xa.z) & ~prmt(mA, 0, 0xAAAA));
        oa.w = __uint_as_float(__float_as_uint(xa.w) & ~prmt(mA, 0, 0xBBBB));
        ob.x = __uint_as_float(__float_as_uint(xb.x) & ~prmt(mB, 0, 0x8888));
        ob.y = __uint_as_float(__float_as_uint(xb.y) & ~prmt(mB, 0, 0x9999));
        ob.z = __uint_as_float(__float_as_uint(xb.z) & ~prmt(mB, 0, 0xAAAA));
        ob.w = __uint_as_float(__float_as_uint(xb.w) & ~prmt(mB, 0, 0xBBBB));

        float4* go = (float4*)gop;
        __stcs(go,     oa);
        __stcs(go + 1, ob);

        vrow += 16 * (ROWB / 8);        // 16 rows in uint2 units
        gp  += 16 * W;
        gop += 16 * W;
    }
}

extern "C" void kernel_launch(void* const* d_in, const int* in_sizes, int n_in,
                              void* d_out, int out_size) {
    const float* x = (const float*)d_in[0];
    float* out = (float*)d_out;
    const int H = 1024, W = 1024;
    const int planes = out_size / (H * W);   // B*C = 48
    dim3 grid(W / TILE_W, H / TILE_H, planes);
    backedge_kernel<<<grid, NTHREADS>>>(x, out, H, W);
}

// round 14
// speedup vs baseline: 1.1014x; 1.1014x over previous
#include <cuda_runtime.h>

// BackEdgeConv2d fused: out = x * !(5 <= boxcount7x7(x >= 128/255, reflect) <= 19)
// x: [16,3,1024,1024] fp32. R12 memory shapes; rows padded to 144B; phase 2
// upgraded to uint4 grid-stride (half the LSU instructions, same wavefronts).

#define TILE_W 128
#define TILE_H 64
#define KPAD 3
#define PH (TILE_H + 2*KPAD)        // 70 padded rows
#define WPR 36                      // words per row (144 B); bytes 0..135 valid
#define ROWB 144
#define PPR 18                      // uint2 pairs per row (pair 17 = zero tail)
#define U4PR 9                      // uint4 per row
#define NTHREADS 256

// PTX prmt: guaranteed default-mode semantics incl. selector-bit-3 MSB-replicate.
__device__ __forceinline__ unsigned prmt(unsigned a, unsigned b, unsigned s) {
    unsigned r;
    asm("prmt.b32 %0, %1, %2, %3;" : "=r"(r) : "r"(a), "r"(b), "r"(s));
    return r;
}

__device__ __forceinline__ unsigned pack4(float4 v, float T) {
    // cond = (x >= T) = !signbit(x - T); x==T -> +0 -> 1. Exact.
    unsigned a0 = __float_as_uint(v.x - T);
    unsigned a1 = __float_as_uint(v.y - T);
    unsigned a2 = __float_as_uint(v.z - T);
    unsigned a3 = __float_as_uint(v.w - T);
    unsigned sa = prmt(prmt(a0, a1, 0x0073), prmt(a2, a3, 0x0073), 0x5410);
    return ((~sa) & 0x80808080u) >> 7;          // 1/0 per byte
}

__global__ __launch_bounds__(NTHREADS, 7)
void backedge_kernel(const float* __restrict__ x, float* __restrict__ out,
                     int H, int W) {
    __shared__ __align__(16) unsigned int scond[PH * WPR];      // 10080 B
    __shared__ __align__(16) unsigned int svsum[TILE_H * WPR];  // 9216 B

    const int tid = threadIdx.x;
    const int c0 = blockIdx.x * TILE_W;
    const int r0 = blockIdx.y * TILE_H;
    const long long plane = (long long)blockIdx.z * H * W;
    const float* xp = x + plane;
    float* op = out + plane;
    const float T = 128.0f / 255.0f;

    // ---- Phase 1: padded binary cond map; one word-PAIR (8 px) per task.
    //      cond byte j <-> global col (c0 - 4 + j); pair 17 (bytes 136..143) = 0.
    const bool interior = (c0 >= 4) && (c0 + TILE_W + 4 <= W) &&
                          (r0 >= KPAD) && (r0 + TILE_H + KPAD <= H);
    if (interior) {
        const float* base = xp + (r0 - KPAD) * W + (c0 - 4);
        #pragma unroll 1
        for (int t = tid; t < PH * PPR; t += NTHREADS) {
            int pr = t / PPR;                 // const divisor -> mul.hi
            int pw = t - pr * PPR;
            uint2 cw = make_uint2(0u, 0u);
            if (pw < 17) {
                const float4* p = (const float4*)(base + pr * W + (pw << 3));
                float4 va = p[0], vb = p[1];
                cw.x = pack4(va, T);
                cw.y = pack4(vb, T);
            }
            ((uint2*)scond)[t] = cw;
        }
    } else {
        #pragma unroll 1
        for (int t = tid; t < PH * PPR; t += NTHREADS) {
            int pr = t / PPR;
            int pw = t - pr * PPR;
            uint2 cw = make_uint2(0u, 0u);
            if (pw < 17) {
                int gr = r0 + pr - KPAD;
                int gc = c0 + (pw << 3) - 4;
                float4 va, vb;
                if ((unsigned)gr < (unsigned)H && (unsigned)gc <= (unsigned)(W - 8)) {
                    const float4* p = (const float4*)(xp + gr * W + gc);
                    va = p[0]; vb = p[1];
                } else {
                    int rr = gr < 0 ? -gr : (gr >= H ? 2 * H - 2 - gr : gr);
                    const float* rowp = xp + rr * W;
                    float f[8];
                    #pragma unroll
                    for (int k = 0; k < 8; k++) {
                        int g = gc + k;
                        g = g < 0 ? -g : (g >= W ? 2 * W - 2 - g : g);
                        f[k] = rowp[g];
                    }
                    va = make_float4(f[0], f[1], f[2], f[3]);
                    vb = make_float4(f[4], f[5], f[6], f[7]);
                }
                cw.x = pack4(va, T);
                cw.y = pack4(vb, T);
            }
            ((uint2*)scond)[t] = cw;
        }
    }
    __syncthreads();

    // ---- Phase 2: vertical 7-sum, SIMD bytes, uint4 grid-stride.
    //      576 tasks; 7 LDS.128 + 1 STS.128 each. Byte adds carry-free (<=7).
    {
        const uint4* c4 = (const uint4*)scond;
        uint4* v4 = (uint4*)svsum;
        #pragma unroll 1
        for (int wi = tid; wi < TILE_H * U4PR; wi += NTHREADS) {
            uint4 s = c4[wi];
            #pragma unroll
            for (int k = 1; k < 7; k++) {
                uint4 a = c4[wi + k * U4PR];
                s.x += a.x; s.y += a.y; s.z += a.z; s.w += a.w;
            }
            v4[wi] = s;
        }
    }
    __syncthreads();

    // ---- Phase 3: R12 verbatim (4 px/thread, warp = one 128-px row):
    //      SIMD prefix-sum horizontal + byte band mask + prmt select.
    const int tx = tid & 31;        // word group -> cols [4tx .. 4tx+3]
    const int ty = tid >> 5;
    const unsigned char* vsb = (const unsigned char*)svsum;
    const unsigned int* vrow = (const unsigned int*)(vsb + ty * ROWB) + tx;
    const float* gp = xp + (long long)(r0 + ty) * W + c0 + (tx << 2);
    float* gop = op + (long long)(r0 + ty) * W + c0 + (tx << 2);

    #pragma unroll
    for (int rr = 0; rr < TILE_H; rr += 8) {
        unsigned w0 = vrow[0];
        unsigned w1 = vrow[1];
        unsigned w2 = vrow[2];

        // byte prefix sums over span a0..a11 (w0,w1,w2); P <= 84 < 128
        unsigned p0 = w0 * 0x01010101u;                       // P0..P3
        unsigned p1 = w1 * 0x01010101u + prmt(p0, 0, 0x3333); // P4..P7
        unsigned p2 = w2 * 0x01010101u + prmt(p1, 0, 0x3333); // P8..P11
        // h_i = P[i+7] - P[i], i = 0..3  (window bytes a_{i+1}..a_{i+7})
        unsigned hA = __vsub4(prmt(p1, p2, 0x6543), p0);

        // band 5..19 per byte -> MSB flag (h <= 49, carry-free)
        unsigned mA = (hA + 0x7B7B7B7Bu) & ~(hA + 0x6C6C6C6Cu) & 0x80808080u;

        float4 xv = *(const float4*)gp;
        float4 ov;
        ov.x = __uint_as_float(__float_as_uint(xv.x) & ~prmt(mA, 0, 0x8888));
        ov.y = __uint_as_float(__float_as_uint(xv.y) & ~prmt(mA, 0, 0x9999));
        ov.z = __uint_as_float(__float_as_uint(xv.z) & ~prmt(mA, 0, 0xAAAA));
        ov.w = __uint_as_float(__float_as_uint(xv.w) & ~prmt(mA, 0, 0xBBBB));

        __stcs((float4*)gop, ov);

        vrow += 8 * (ROWB / 4);     // 8 rows in word units
        gp  += 8 * W;
        gop += 8 * W;
    }
}

extern "C" void kernel_launch(void* const* d_in, const int* in_sizes, int n_in,
                              void* d_out, int out_size) {
    const float* x = (const float*)d_in[0];
    float* out = (float*)d_out;
    const int H = 1024, W = 1024;
    const int planes = out_size / (H * W);   // B*C = 48
    dim3 grid(W / TILE_W, H / TILE_H, planes);
    backedge_kernel<<<grid, NTHREADS>>>(x, out, H, W);
}

// round 15
// speedup vs baseline: 1.1666x; 1.0592x over previous
#include <cuda_runtime.h>

// BackEdgeConv2d fused: out = x * !(5 <= boxcount7x7(x >= 128/255, reflect) <= 19)
// x: [16,3,1024,1024] fp32. Bit-packed cond map (1 bit/px): phase 1 packs 8 px
// to one byte via dp4a; phase 2 does bitwise CSA vertical sums + bit->byte
// expansion; phase 3 = R12 verbatim (SIMD prefix-sum + prmt mask).

#define TILE_W 128
#define TILE_H 64
#define KPAD 3
#define PH (TILE_H + 2*KPAD)        // 70 padded rows
#define CSTRIDE 24                  // cond row stride in BYTES (17 valid bytes)
#define ROWB 144                    // svsum row stride in bytes (34 valid words)
#define NTHREADS 256

// PTX prmt: guaranteed default-mode semantics incl. selector-bit-3 MSB-replicate.
__device__ __forceinline__ unsigned prmt(unsigned a, unsigned b, unsigned s) {
    unsigned r;
    asm("prmt.b32 %0, %1, %2, %3;" : "=r"(r) : "r"(a), "r"(b), "r"(s));
    return r;
}

__device__ __forceinline__ unsigned pack4(float4 v, float T) {
    // cond = (x >= T) = !signbit(x - T); x==T -> +0 -> 1. Exact. 0/1 per byte.
    unsigned a0 = __float_as_uint(v.x - T);
    unsigned a1 = __float_as_uint(v.y - T);
    unsigned a2 = __float_as_uint(v.z - T);
    unsigned a3 = __float_as_uint(v.w - T);
    unsigned sa = prmt(prmt(a0, a1, 0x0073), prmt(a2, a3, 0x0073), 0x5410);
    return ((~sa) & 0x80808080u) >> 7;
}

// Expand 8-bit mask to 8 bytes: byte m = bit m, scaled by (0x80 >> sh).
// rev8(b)*MAGIC puts b_m at bit (8m+7); positions k+9m are unique -> no carries.
__device__ __forceinline__ unsigned long long bitexp(unsigned b, int sh) {
    unsigned rev = __brev(b) >> 24;
    unsigned long long p = (unsigned long long)rev * 0x8040201008040201ULL;
    return (p & 0x8080808080808080ULL) >> sh;
}

__global__ __launch_bounds__(NTHREADS, 7)
void backedge_kernel(const float* __restrict__ x, float* __restrict__ out,
                     int H, int W) {
    __shared__ __align__(16) unsigned char scondb[PH * CSTRIDE];  // 1680 B
    __shared__ __align__(16) unsigned int svsum[TILE_H * (ROWB/4)]; // 9216 B

    const int tid = threadIdx.x;
    const int c0 = blockIdx.x * TILE_W;
    const int r0 = blockIdx.y * TILE_H;
    const long long plane = (long long)blockIdx.z * H * W;
    const float* xp = x + plane;
    float* op = out + plane;
    const float T = 128.0f / 255.0f;

    // ---- Phase 1: bit-packed cond map. Task (pr, j), j = 0..16:
    //      byte j of row pr holds cond bits for px cols (c0 + 8j - 4 + k), k=0..7.
    const bool interior = (c0 >= 4) && (c0 + TILE_W + 4 <= W) &&
                          (r0 >= KPAD) && (r0 + TILE_H + KPAD <= H);
    if (interior) {
        const float* base = xp + (r0 - KPAD) * W + (c0 - 4);
        #pragma unroll 1
        for (int t = tid; t < PH * 17; t += NTHREADS) {
            int pr = t / 17;                  // const divisor -> mul.hi
            int j  = t - pr * 17;
            const float4* p = (const float4*)(base + pr * W + (j << 3));
            float4 va = p[0], vb = p[1];
            unsigned w0 = pack4(va, T);       // px 8j-4 .. 8j-1 as 0/1 bytes
            unsigned w1 = pack4(vb, T);       // px 8j   .. 8j+3
            unsigned b = __dp4a(w1, 0x80402010u, __dp4a(w0, 0x08040201u, 0u));
            scondb[pr * CSTRIDE + j] = (unsigned char)b;
        }
    } else {
        #pragma unroll 1
        for (int t = tid; t < PH * 17; t += NTHREADS) {
            int pr = t / 17;
            int j  = t - pr * 17;
            int gr = r0 + pr - KPAD;
            int gc = c0 + (j << 3) - 4;
            float4 va, vb;
            if ((unsigned)gr < (unsigned)H && (unsigned)gc <= (unsigned)(W - 8)) {
                const float4* p = (const float4*)(xp + gr * W + gc);
                va = p[0]; vb = p[1];
            } else {
                int rr = gr < 0 ? -gr : (gr >= H ? 2 * H - 2 - gr : gr);
                const float* rowp = xp + rr * W;
                float f[8];
                #pragma unroll
                for (int k = 0; k < 8; k++) {
                    int g = gc + k;
                    g = g < 0 ? -g : (g >= W ? 2 * W - 2 - g : g);
                    f[k] = rowp[g];
                }
                va = make_float4(f[0], f[1], f[2], f[3]);
                vb = make_float4(f[4], f[5], f[6], f[7]);
            }
            unsigned w0 = pack4(va, T);
            unsigned w1 = pack4(vb, T);
            unsigned b = __dp4a(w1, 0x80402010u, __dp4a(w0, 0x08040201u, 0u));
            scondb[pr * CSTRIDE + j] = (unsigned char)b;
        }
    }
    __syncthreads();

    // ---- Phase 2: vertical 7-sum per pixel via bitwise CSA on cond bytes,
    //      then bit->byte expansion. Task (r, c): svsum bytes 8c..8c+7 of row r.
    #pragma unroll 1
    for (int t = tid; t < TILE_H * 17; t += NTHREADS) {
        int r = t / 17;                       // const divisor
        int c = t - r * 17;
        const unsigned char* cb = scondb + r * CSTRIDE + c;
        unsigned b0 = cb[0];
        unsigned b1 = cb[CSTRIDE];
        unsigned b2 = cb[2 * CSTRIDE];
        unsigned b3 = cb[3 * CSTRIDE];
        unsigned b4 = cb[4 * CSTRIDE];
        unsigned b5 = cb[5 * CSTRIDE];
        unsigned b6 = cb[6 * CSTRIDE];

        // 5-CSA tree: count per bit = s0 + 2*s1 + 4*s2
        unsigned t1 = b0 ^ b1;
        unsigned c1 = (b0 & b1) | (b2 & t1);
        unsigned u  = t1 ^ b2;
        unsigned t2 = b3 ^ b4;
        unsigned c2 = (b3 & b4) | (b5 & t2);
        unsigned v  = t2 ^ b5;
        unsigned t3 = u ^ v;
        unsigned c3 = (u & v) | (b6 & t3);
        unsigned s0 = t3 ^ b6;
        unsigned t4 = c1 ^ c2;
        unsigned s2 = (c1 & c2) | (c3 & t4);
        unsigned s1 = t4 ^ c3;

        unsigned long long vsum = bitexp(s0, 7) + bitexp(s1, 6) + bitexp(s2, 5);
        *(unsigned long long*)((char*)svsum + r * ROWB + (c << 3)) = vsum;
    }
    __syncthreads();

    // ---- Phase 3: R12 verbatim (4 px/thread, warp = one 128-px row):
    //      SIMD prefix-sum horizontal + byte band mask + prmt select.
    const int tx = tid & 31;        // word group -> cols [4tx .. 4tx+3]
    const int ty = tid >> 5;
    const unsigned char* vsb = (const unsigned char*)svsum;
    const unsigned int* vrow = (const unsigned int*)(vsb + ty * ROWB) + tx;
    const float* gp = xp + (long long)(r0 + ty) * W + c0 + (tx << 2);
    float* gop = op + (long long)(r0 + ty) * W + c0 + (tx << 2);

    #pragma unroll
    for (int rr = 0; rr < TILE_H; rr += 8) {
        unsigned w0 = vrow[0];
        unsigned w1 = vrow[1];
        unsigned w2 = vrow[2];

        // byte prefix sums over span a0..a11 (w0,w1,w2); P <= 84 < 128
        unsigned p0 = w0 * 0x01010101u;                       // P0..P3
        unsigned p1 = w1 * 0x01010101u + prmt(p0, 0, 0x3333); // P4..P7
        unsigned p2 = w2 * 0x01010101u + prmt(p1, 0, 0x3333); // P8..P11
        // h_i = P[i+7] - P[i], i = 0..3  (window bytes a_{i+1}..a_{i+7})
        unsigned hA = __vsub4(prmt(p1, p2, 0x6543), p0);

        // band 5..19 per byte -> MSB flag (h <= 49, carry-free)
        unsigned mA = (hA + 0x7B7B7B7Bu) & ~(hA + 0x6C6C6C6Cu) & 0x80808080u;

        float4 xv = *(const float4*)gp;
        float4 ov;
        ov.x = __uint_as_float(__float_as_uint(xv.x) & ~prmt(mA, 0, 0x8888));
        ov.y = __uint_as_float(__float_as_uint(xv.y) & ~prmt(mA, 0, 0x9999));
        ov.z = __uint_as_float(__float_as_uint(xv.z) & ~prmt(mA, 0, 0xAAAA));
        ov.w = __uint_as_float(__float_as_uint(xv.w) & ~prmt(mA, 0, 0xBBBB));

        __stcs((float4*)gop, ov);

        vrow += 8 * (ROWB / 4);     // 8 rows in word units
        gp  += 8 * W;
        gop += 8 * W;
    }
}

extern "C" void kernel_launch(void* const* d_in, const int* in_sizes, int n_in,
                              void* d_out, int out_size) {
    const float* x = (const float*)d_in[0];
    float* out = (float*)d_out;
    const int H = 1024, W = 1024;
    const int planes = out_size / (H * W);   // B*C = 48
    dim3 grid(W / TILE_W, H / TILE_H, planes);
    backedge_kernel<<<grid, NTHREADS>>>(x, out, H, W);
}